// round 12
// baseline (speedup 1.0000x reference)
#include <cuda_runtime.h>
#include <cuda_fp16.h>
#include <cstdint>

// ---------------- problem constants ----------------
#define NQ      8
#define EMBED   512
#define FFN     2048
#define KC      128           // K-chunk over FFN
#define NCHUNK  16            // FFN / KC
#define THREADS 256
#define NCTAS   1024          // 256 token tiles x 4 N-quarters

// ---------------- smem layout (bytes) ----------------
#define SM_B    0             // 3 x 32768 : 128 rows x 256B fp16 (swizzled), 3-stage ring
#define SM_Q    98304         // 128 rows x 16B fp16 (q, k-contig)
#define SMEM_TOTAL 100352

// fp16 scratch (allowed path: __device__ globals)
__device__ __half g_W2h[EMBED * FFN];
__device__ __half g_W1h[FFN * NQ];

// ---------------- helpers ----------------
__device__ __forceinline__ uint32_t smem_u32(const void* p) {
    uint32_t a;
    asm("{ .reg .u64 t; cvta.to.shared.u64 t, %1; cvt.u32.u64 %0, t; }" : "=r"(a) : "l"(p));
    return a;
}

#define CP_ASYNC_16(dst, src) \
    asm volatile("cp.async.cg.shared.global [%0], [%1], 16;" :: "r"((uint32_t)(dst)), "l"(src) : "memory")
#define CP_COMMIT() asm volatile("cp.async.commit_group;" ::: "memory")

#define BAR_HALF(id) \
    asm volatile("bar.sync %0, 128;" :: "r"(id) : "memory")

#define LDSM_X4(r0, r1, r2, r3, addr) \
    asm volatile("ldmatrix.sync.aligned.m8n8.x4.shared.b16 {%0,%1,%2,%3}, [%4];" \
                 : "=r"(r0), "=r"(r1), "=r"(r2), "=r"(r3) : "r"(addr))
#define LDSM_X2(r0, r1, addr) \
    asm volatile("ldmatrix.sync.aligned.m8n8.x2.shared.b16 {%0,%1}, [%2];" \
                 : "=r"(r0), "=r"(r1) : "r"(addr))

// mma m16n8k16 row.col f32 += f16*f16
__device__ __forceinline__ void hmma16(float* d, const uint32_t* a, const uint32_t* b) {
    asm volatile("mma.sync.aligned.m16n8k16.row.col.f32.f16.f16.f32 "
                 "{%0,%1,%2,%3}, {%4,%5,%6,%7}, {%8,%9}, {%0,%1,%2,%3};"
                 : "+f"(d[0]), "+f"(d[1]), "+f"(d[2]), "+f"(d[3])
                 : "r"(a[0]), "r"(a[1]), "r"(a[2]), "r"(a[3]), "r"(b[0]), "r"(b[1]));
}
// mma m16n8k8 row.col f32 += f16*f16  (h = relu(q . W1^T), K=8) — C=0 start
__device__ __forceinline__ void hmma8z(float* d, const uint32_t* a, uint32_t b) {
    asm volatile("mma.sync.aligned.m16n8k8.row.col.f32.f16.f16.f32 "
                 "{%0,%1,%2,%3}, {%4,%5}, {%6}, {%7,%7,%7,%7};"
                 : "=f"(d[0]), "=f"(d[1]), "=f"(d[2]), "=f"(d[3])
                 : "r"(a[0]), "r"(a[1]), "r"(b), "f"(0.0f));
}

// pack two f32 to f16x2, relu via max.f16x2 (1 ALU op)
__device__ __forceinline__ uint32_t prelu_h2(float a, float b) {
    __half2 h = __floats2half2_rn(a, b);
    uint32_t u = *reinterpret_cast<uint32_t*>(&h);
    asm("max.f16x2 %0, %0, %1;" : "+r"(u) : "r"(0u));
    return u;
}

// compute A-frags (m16n8k16 A layout) for one k16-step from q and two W1 b-frags
__device__ __forceinline__ void compute_A(uint32_t A[2][4], const uint32_t aq[2][2],
                                          uint32_t w1lo, uint32_t w1hi) {
    #pragma unroll
    for (int mb = 0; mb < 2; mb++) {
        float h0[4], h1[4];
        hmma8z(h0, aq[mb], w1lo);
        hmma8z(h1, aq[mb], w1hi);
        A[mb][0] = prelu_h2(h0[0], h0[1]);
        A[mb][1] = prelu_h2(h0[2], h0[3]);
        A[mb][2] = prelu_h2(h1[0], h1[1]);
        A[mb][3] = prelu_h2(h1[2], h1[3]);
    }
}

// ---------------- W2 / W1 fp32 -> fp16 ----------------
__global__ void __launch_bounds__(256) wcvt_kernel(const float* __restrict__ W2,
                                                   const float* __restrict__ W1) {
    size_t i = ((size_t)blockIdx.x * blockDim.x + threadIdx.x) * 4;
    float4 v = *reinterpret_cast<const float4*>(W2 + i);
    __half2* d = reinterpret_cast<__half2*>(g_W2h + i);
    d[0] = __floats2half2_rn(v.x, v.y);
    d[1] = __floats2half2_rn(v.z, v.w);
    if (blockIdx.x < 16) {   // 16 x 256 x 4 = 16384 = FFN*NQ
        size_t j = ((size_t)blockIdx.x * 256 + threadIdx.x) * 4;
        float4 w = *reinterpret_cast<const float4*>(W1 + j);
        __half2* e = reinterpret_cast<__half2*>(g_W1h + j);
        e[0] = __floats2half2_rn(w.x, w.y);
        e[1] = __floats2half2_rn(w.z, w.w);
    }
}

// ---------------- fused main kernel ----------------
__global__ void __launch_bounds__(THREADS, 2)
ffq_mma(const float* __restrict__ x, const float* __restrict__ theta,
        float* __restrict__ out) {
    extern __shared__ char smem[];
    const uint32_t sb = smem_u32(smem);
    const int tid   = threadIdx.x;
    const int lane  = tid & 31;
    const int warp  = tid >> 5;
    const int tile  = blockIdx.x >> 2;     // token tile (128 tokens)
    const int nq    = blockIdx.x & 3;      // embed quarter (128 cols)

    // warp layout: 4(M) x 2(N); warp tile 32(M) x 64(N)
    const int mrow0 = (warp & 3) * 32;
    const int n0w   = (warp >> 2) * 64;
    const int half  = tid >> 7;            // B rows are half-local (produce == consume)

    // ---- B ring cp.async identity: thread owns a 128B half of one 256B row ----
    const int brow  = tid >> 1;            // 0..127  (W2 row within quarter)
    const int bhalf = tid & 1;
    const char* w2row = (const char*)g_W2h +
        ((size_t)(nq * 128 + brow) * FFN) * 2 + bhalf * 128;
    const uint32_t bswr = (uint32_t)(brow & 15) << 4;
    const uint32_t bdst = sb + SM_B + brow * 256 + (bhalf ? ((uint32_t)128 ^ bswr) - 128u + 128u : 0u);

    // (plain form below; bdst above unused to keep addressing obvious)
    const uint32_t brow_base = sb + SM_B + brow * 256;

    // issue copies for chunks 0 and 1 ASAP
    #pragma unroll
    for (int p = 0; p < 2; p++) {
        const char* src = w2row + (size_t)p * (KC * 2);
        uint32_t d0 = brow_base + p * 32768;
        #pragma unroll
        for (int i = 0; i < 8; i++) {
            uint32_t c = (uint32_t)(bhalf * 128 + i * 16);
            CP_ASYNC_16(d0 + (c ^ bswr), src + i * 16);
        }
        CP_COMMIT();
    }

    // ---- quantum features -> smem q[128][8] fp16 (16B rows) ----
    {
        int tok = tid >> 1, hf = tid & 1;
        const float* xp = x + ((size_t)tile * 128 + tok) * EMBED + hf * 4;
        float4 v  = *reinterpret_cast<const float4*>(xp);
        float4 tv = *reinterpret_cast<const float4*>(theta + hf * 4);
        __half2 a = __floats2half2_rn(cosf(2.f * v.x + tv.x), cosf(2.f * v.y + tv.y));
        __half2 b = __floats2half2_rn(cosf(2.f * v.z + tv.z), cosf(2.f * v.w + tv.w));
        uint32_t u0 = *reinterpret_cast<uint32_t*>(&a);
        uint32_t u1 = *reinterpret_cast<uint32_t*>(&b);
        asm volatile("st.shared.v2.b32 [%0], {%1,%2};"
                     :: "r"(sb + SM_Q + tok * 16 + hf * 8), "r"(u0), "r"(u1) : "memory");
    }
    __syncthreads();   // q visible to all (only full-CTA barrier in the kernel)

    // ---- resident q A-frags (m16n8k8): warp's own 2 m-tiles ----
    uint32_t aq[2][2];
    {
        uint32_t addr = sb + SM_Q + (mrow0 + (lane & 15)) * 16;
        LDSM_X2(aq[0][0], aq[0][1], addr);
        LDSM_X2(aq[1][0], aq[1][1], addr + 256);
    }

    // W1 b-frag base: lane T covers (f = g*8 + T/4, q = 2(T%4), 2(T%4)+1)
    const char* w1base = (const char*)g_W1h + (size_t)(lane >> 2) * 16 + (lane & 3) * 4;

    // accumulators: 2 m16 x 8 n8 x 4 f32 = 64 regs
    float acc[2][8][4];
    #pragma unroll
    for (int mb = 0; mb < 2; mb++)
        #pragma unroll
        for (int nb = 0; nb < 8; nb++)
            #pragma unroll
            for (int i = 0; i < 4; i++) acc[mb][nb][i] = 0.0f;

    // ldmatrix B lane addressing (m16n8k16 B-frag via x4, non-trans)
    const int rowB = (lane & 7) + ((lane >> 4) & 1) * 8;
    const int khB  = (lane >> 3) & 1;

    // ---- A-frag ping-pong + rolling 2-deep w1 pipeline ----
    uint32_t Afr[2][2][4];
    uint32_t w1a, w1b;
    // step 0 frags -> A slot 0
    w1a = *reinterpret_cast<const uint32_t*>(w1base);
    w1b = *reinterpret_cast<const uint32_t*>(w1base + 128);
    compute_A(Afr[0], aq, w1a, w1b);
    // step 1 frags staged
    w1a = *reinterpret_cast<const uint32_t*>(w1base + 256);
    w1b = *reinterpret_cast<const uint32_t*>(w1base + 256 + 128);

    for (int k = 0; k < NCHUNK; k++) {
        const uint32_t bbuf = sb + SM_B + (k % 3) * 32768;

        // own group-k copies done (group k+1 may stay in flight)
        if (k < NCHUNK - 1) { asm volatile("cp.async.wait_group 1;" ::: "memory"); }
        else                { asm volatile("cp.async.wait_group 0;" ::: "memory"); }
        // half-CTA barrier: B rows are produced & consumed within the half;
        // also certifies chunk k-1 fully read by the half -> slot (k+2)%3 free
        BAR_HALF(1 + half);

        // ---- issue cp.async for chunk k+2 into slot (k+2)%3 ----
        if (k + 2 < NCHUNK) {
            const char* src = w2row + (size_t)(k + 2) * (KC * 2);
            uint32_t d0 = brow_base + ((k + 2) % 3) * 32768;
            #pragma unroll
            for (int i = 0; i < 8; i++) {
                uint32_t c = (uint32_t)(bhalf * 128 + i * 16);
                CP_ASYNC_16(d0 + (c ^ bswr), src + i * 16);
            }
            CP_COMMIT();
        }

        // ---- 8 k16-steps, fully pipelined ----
        #pragma unroll
        for (int kk = 0; kk < 8; kk++) {
            const int cur = kk & 1, nxt = cur ^ 1;
            const int s = k * 8 + kk;

            // B frags for this step (LDSM latency covered by compute_A below)
            uint32_t Bf[8][2];
            #pragma unroll
            for (int j = 0; j < 4; j++) {
                int r = n0w + j * 16 + rowB;
                uint32_t addr = bbuf + (uint32_t)r * 256 +
                                (((uint32_t)(kk * 32 + khB * 16)) ^ ((uint32_t)(r & 15) << 4));
                LDSM_X4(Bf[2 * j][0], Bf[2 * j][1], Bf[2 * j + 1][0], Bf[2 * j + 1][1], addr);
            }

            // A-frags for step s+1 (hmma8 + pack fill the LDSM shadow)
            compute_A(Afr[nxt], aq, w1a, w1b);

            // w1 frags for step s+2 (LDG latency hidden under the hmma16 block)
            {
                int sn = s + 2; if (sn > NCHUNK * 8 - 1) sn = NCHUNK * 8 - 1;
                w1a = *reinterpret_cast<const uint32_t*>(w1base + (size_t)sn * 256);
                w1b = *reinterpret_cast<const uint32_t*>(w1base + (size_t)sn * 256 + 128);
            }

            // main hmma block
            #pragma unroll
            for (int mb = 0; mb < 2; mb++)
                #pragma unroll
                for (int nb = 0; nb < 8; nb++)
                    hmma16(acc[mb][nb], Afr[cur][mb], Bf[nb]);
        }
    }

    // ---- epilogue ----
    #pragma unroll
    for (int mb = 0; mb < 2; mb++) {
        int r = mrow0 + mb * 16 + (lane >> 2);
        size_t gt = (size_t)tile * 128 + r;
        float* row0 = out + gt * EMBED + nq * 128 + n0w;
        float* row1 = row0 + 8 * EMBED;
        #pragma unroll
        for (int nb = 0; nb < 8; nb++) {
            int c = nb * 8 + (lane & 3) * 2;
            *reinterpret_cast<float2*>(row0 + c) = make_float2(acc[mb][nb][0], acc[mb][nb][1]);
            *reinterpret_cast<float2*>(row1 + c) = make_float2(acc[mb][nb][2], acc[mb][nb][3]);
        }
    }
}

// ---------------- launch ----------------
extern "C" void kernel_launch(void* const* d_in, const int* in_sizes, int n_in,
                              void* d_out, int out_size) {
    const float* x     = (const float*)d_in[0];
    const float* theta = (const float*)d_in[1];
    const float* W1    = (const float*)d_in[2];
    const float* W2    = (const float*)d_in[3];
    float* out = (float*)d_out;

    cudaFuncSetAttribute(ffq_mma, cudaFuncAttributeMaxDynamicSharedMemorySize, SMEM_TOTAL);

    // W2/W1 fp32 -> fp16 scratch (deterministic each call)
    wcvt_kernel<<<(EMBED * FFN) / (256 * 4), 256>>>(W2, W1);

    // fused GEMM: 1024 CTAs = 256 token tiles x 4 N-quarters, 2 CTAs/SM
    ffq_mma<<<NCTAS, THREADS, SMEM_TOTAL>>>(x, theta, out);
}

// round 13
// speedup vs baseline: 1.2921x; 1.2921x over previous
#include <cuda_runtime.h>
#include <cuda_fp16.h>
#include <cstdint>

// ---------------- problem constants ----------------
#define NQ      8
#define EMBED   512
#define FFN     2048
#define KC      64            // K-chunk over FFN
#define NCHUNK  32            // FFN / KC
#define THREADS 256
#define NCTAS   1024          // 256 token tiles x 4 N-quarters

// ---------------- smem layout (bytes) ----------------
#define SM_B    0             // 3 x 16384 : 128 rows x 128B fp16 (swizzled), 3-stage ring
#define SM_Q    49152         // 128 rows x 16B fp16 (q, k-contig)
#define SMEM_TOTAL 51200

// fp16 scratch (allowed path: __device__ globals)
__device__ __half g_W2h[EMBED * FFN];
__device__ __half g_W1h[FFN * NQ];

// ---------------- helpers ----------------
__device__ __forceinline__ uint32_t smem_u32(const void* p) {
    uint32_t a;
    asm("{ .reg .u64 t; cvta.to.shared.u64 t, %1; cvt.u32.u64 %0, t; }" : "=r"(a) : "l"(p));
    return a;
}

#define CP_ASYNC_16(dst, src) \
    asm volatile("cp.async.cg.shared.global [%0], [%1], 16;" :: "r"((uint32_t)(dst)), "l"(src) : "memory")
#define CP_COMMIT() asm volatile("cp.async.commit_group;" ::: "memory")

#define LDSM_X4(r0, r1, r2, r3, addr) \
    asm volatile("ldmatrix.sync.aligned.m8n8.x4.shared.b16 {%0,%1,%2,%3}, [%4];" \
                 : "=r"(r0), "=r"(r1), "=r"(r2), "=r"(r3) : "r"(addr))
#define LDSM_X2(r0, r1, addr) \
    asm volatile("ldmatrix.sync.aligned.m8n8.x2.shared.b16 {%0,%1}, [%2];" \
                 : "=r"(r0), "=r"(r1) : "r"(addr))

// mma m16n8k16 row.col f32 += f16*f16
__device__ __forceinline__ void hmma16(float* d, const uint32_t* a, const uint32_t* b) {
    asm volatile("mma.sync.aligned.m16n8k16.row.col.f32.f16.f16.f32 "
                 "{%0,%1,%2,%3}, {%4,%5,%6,%7}, {%8,%9}, {%0,%1,%2,%3};"
                 : "+f"(d[0]), "+f"(d[1]), "+f"(d[2]), "+f"(d[3])
                 : "r"(a[0]), "r"(a[1]), "r"(a[2]), "r"(a[3]), "r"(b[0]), "r"(b[1]));
}
// mma m16n8k8 row.col f32 += f16*f16  (h = relu(q . W1^T), K=8) — C=0 start
__device__ __forceinline__ void hmma8z(float* d, const uint32_t* a, uint32_t b) {
    asm volatile("mma.sync.aligned.m16n8k8.row.col.f32.f16.f16.f32 "
                 "{%0,%1,%2,%3}, {%4,%5}, {%6}, {%7,%7,%7,%7};"
                 : "=f"(d[0]), "=f"(d[1]), "=f"(d[2]), "=f"(d[3])
                 : "r"(a[0]), "r"(a[1]), "r"(b), "f"(0.0f));
}

// pack two f32 to f16x2, relu via max.f16x2 (1 ALU op)
__device__ __forceinline__ uint32_t prelu_h2(float a, float b) {
    __half2 h = __floats2half2_rn(a, b);
    uint32_t u = *reinterpret_cast<uint32_t*>(&h);
    asm("max.f16x2 %0, %0, %1;" : "+r"(u) : "r"(0u));
    return u;
}

// compute A-frag (m16n8k16 A layout, one m16 tile) for one k16-step
__device__ __forceinline__ void compute_A(uint32_t A[4], const uint32_t aq[2],
                                          uint32_t w1lo, uint32_t w1hi) {
    float h0[4], h1[4];
    hmma8z(h0, aq, w1lo);
    hmma8z(h1, aq, w1hi);
    A[0] = prelu_h2(h0[0], h0[1]);
    A[1] = prelu_h2(h0[2], h0[3]);
    A[2] = prelu_h2(h1[0], h1[1]);
    A[3] = prelu_h2(h1[2], h1[3]);
}

// ---------------- W2 / W1 fp32 -> fp16 ----------------
__global__ void __launch_bounds__(256) wcvt_kernel(const float* __restrict__ W2,
                                                   const float* __restrict__ W1) {
    size_t i = ((size_t)blockIdx.x * blockDim.x + threadIdx.x) * 4;
    float4 v = *reinterpret_cast<const float4*>(W2 + i);
    __half2* d = reinterpret_cast<__half2*>(g_W2h + i);
    d[0] = __floats2half2_rn(v.x, v.y);
    d[1] = __floats2half2_rn(v.z, v.w);
    if (blockIdx.x < 16) {   // 16 x 256 x 4 = 16384 = FFN*NQ
        size_t j = ((size_t)blockIdx.x * 256 + threadIdx.x) * 4;
        float4 w = *reinterpret_cast<const float4*>(W1 + j);
        __half2* e = reinterpret_cast<__half2*>(g_W1h + j);
        e[0] = __floats2half2_rn(w.x, w.y);
        e[1] = __floats2half2_rn(w.z, w.w);
    }
}

// ---------------- fused main kernel ----------------
__global__ void __launch_bounds__(THREADS, 2)
ffq_mma(const float* __restrict__ x, const float* __restrict__ theta,
        float* __restrict__ out) {
    extern __shared__ char smem[];
    const uint32_t sb = smem_u32(smem);
    const int tid   = threadIdx.x;
    const int lane  = tid & 31;
    const int warp  = tid >> 5;
    const int tile  = blockIdx.x >> 2;     // token tile (128 tokens)
    const int nq    = blockIdx.x & 3;      // embed quarter (128 cols)

    // warp layout: 8(M) x 1(N); warp tile 16(M) x 128(N) — A-frags unique per warp
    const int mrow0 = warp * 16;

    // ---- B ring: issue cp.async for chunks 0,1 ASAP ----
    const int brow  = tid >> 1;            // 0..127  (W2 row within quarter)
    const int bhalf = tid & 1;             // 64B half of the 128B row
    const char* w2row = (const char*)g_W2h +
        ((size_t)(nq * 128 + brow) * FFN) * 2 + bhalf * 64;
    const uint32_t bswr = (uint32_t)(brow & 7) << 4;
    const uint32_t bdst = sb + SM_B + brow * 128;
    #pragma unroll
    for (int p = 0; p < 2; p++) {
        const char* src = w2row + (size_t)p * (KC * 2);
        uint32_t d0 = bdst + p * 16384;
        #pragma unroll
        for (int i = 0; i < 4; i++) {
            uint32_t c = bhalf * 64 + i * 16;
            CP_ASYNC_16(d0 + (c ^ bswr), src + i * 16);
        }
        CP_COMMIT();
    }

    // ---- quantum features -> smem q[128][8] fp16 (16B rows) ----
    {
        int tok = tid >> 1, hf = tid & 1;
        const float* xp = x + ((size_t)tile * 128 + tok) * EMBED + hf * 4;
        float4 v  = *reinterpret_cast<const float4*>(xp);
        float4 tv = *reinterpret_cast<const float4*>(theta + hf * 4);
        __half2 a = __floats2half2_rn(cosf(2.f * v.x + tv.x), cosf(2.f * v.y + tv.y));
        __half2 b = __floats2half2_rn(cosf(2.f * v.z + tv.z), cosf(2.f * v.w + tv.w));
        uint32_t u0 = *reinterpret_cast<uint32_t*>(&a);
        uint32_t u1 = *reinterpret_cast<uint32_t*>(&b);
        asm volatile("st.shared.v2.b32 [%0], {%1,%2};"
                     :: "r"(sb + SM_Q + tok * 16 + hf * 8), "r"(u0), "r"(u1) : "memory");
    }
    __syncthreads();

    // ---- resident q A-frag (m16n8k8): warp's single m16 tile ----
    uint32_t aq[2];
    LDSM_X2(aq[0], aq[1], sb + SM_Q + (mrow0 + (lane & 15)) * 16);

    // W1 b-frag base: lane T covers (f = g*8 + T/4, q = 2(T%4), 2(T%4)+1)
    const char* w1base = (const char*)g_W1h + (size_t)(lane >> 2) * 16 + (lane & 3) * 4;

    // accumulators: 16 n8 x 4 f32 = 64 regs
    float acc[16][4];
    #pragma unroll
    for (int nb = 0; nb < 16; nb++)
        #pragma unroll
        for (int i = 0; i < 4; i++) acc[nb][i] = 0.0f;

    // ldmatrix B lane addressing (m16n8k16 B-frag via x4, non-trans)
    const int rowB = (lane & 7) + ((lane >> 4) & 1) * 8;
    const int khB  = (lane >> 3) & 1;

    // ---- W1 frags + A-frags for chunk 0, steps 0..1 (pre-barrier tensor work) ----
    uint32_t w1f[8];
    #pragma unroll
    for (int g = 0; g < 8; g++)
        w1f[g] = *reinterpret_cast<const uint32_t*>(w1base + (size_t)(g * 8) * 16);

    uint32_t A01[2][4];   // steps 0,1
    compute_A(A01[0], aq, w1f[0], w1f[1]);
    compute_A(A01[1], aq, w1f[2], w1f[3]);

    for (int k = 0; k < NCHUNK; k++) {
        const uint32_t bbuf = sb + SM_B + (k % 3) * 16384;

        // own group-k copies done (pending <= 1)
        if (k < NCHUNK - 1) { asm volatile("cp.async.wait_group 1;" ::: "memory"); }
        else                { asm volatile("cp.async.wait_group 0;" ::: "memory"); }
        // all threads' group-k copies visible; chunk k-1 done (slot (k+2)%3 free)
        __syncthreads();

        // ---- issue cp.async for chunk k+2 into slot (k+2)%3 ----
        if (k + 2 < NCHUNK) {
            const char* src = w2row + (size_t)(k + 2) * (KC * 2);
            uint32_t d0 = bdst + ((k + 2) % 3) * 16384;
            #pragma unroll
            for (int i = 0; i < 4; i++) {
                uint32_t c = bhalf * 64 + i * 16;
                CP_ASYNC_16(d0 + (c ^ bswr), src + i * 16);
            }
            CP_COMMIT();
        }

        // ---- steps 0,1: pure LDSM + HMMA (A already resident) ----
        #pragma unroll
        for (int kk = 0; kk < 2; kk++) {
            const uint32_t cb = (uint32_t)(kk * 32 + khB * 16);
            #pragma unroll
            for (int hfn = 0; hfn < 2; hfn++) {          // two n-halves of 64 cols
                uint32_t Bg[8][2];
                #pragma unroll
                for (int j = 0; j < 4; j++) {
                    int r = hfn * 64 + j * 16 + rowB;
                    uint32_t addr = bbuf + (uint32_t)r * 128 + (cb ^ ((uint32_t)(r & 7) << 4));
                    LDSM_X4(Bg[2 * j][0], Bg[2 * j][1], Bg[2 * j + 1][0], Bg[2 * j + 1][1], addr);
                }
                #pragma unroll
                for (int nb = 0; nb < 8; nb++)
                    hmma16(acc[hfn * 8 + nb], A01[kk], Bg[nb]);
            }
        }

        // ---- A-frags for steps 2,3 (independent hmma8 batch) ----
        uint32_t A23[2][4];
        compute_A(A23[0], aq, w1f[4], w1f[5]);
        compute_A(A23[1], aq, w1f[6], w1f[7]);

        // ---- steps 2,3 ----
        #pragma unroll
        for (int kk = 2; kk < 4; kk++) {
            const uint32_t cb = (uint32_t)(kk * 32 + khB * 16);
            #pragma unroll
            for (int hfn = 0; hfn < 2; hfn++) {
                uint32_t Bg[8][2];
                #pragma unroll
                for (int j = 0; j < 4; j++) {
                    int r = hfn * 64 + j * 16 + rowB;
                    uint32_t addr = bbuf + (uint32_t)r * 128 + (cb ^ ((uint32_t)(r & 7) << 4));
                    LDSM_X4(Bg[2 * j][0], Bg[2 * j][1], Bg[2 * j + 1][0], Bg[2 * j + 1][1], addr);
                }
                #pragma unroll
                for (int nb = 0; nb < 8; nb++)
                    hmma16(acc[hfn * 8 + nb], A23[kk - 2], Bg[nb]);
            }
        }

        // ---- prep next chunk: W1 frags + A(0,1), overlapping hmma16 tail ----
        if (k + 1 < NCHUNK) {
            #pragma unroll
            for (int g = 0; g < 8; g++)
                w1f[g] = *reinterpret_cast<const uint32_t*>(
                    w1base + ((size_t)(k + 1) * KC + g * 8) * 16);
            compute_A(A01[0], aq, w1f[0], w1f[1]);
            compute_A(A01[1], aq, w1f[2], w1f[3]);
        }
    }

    // ---- epilogue: warp writes 16 rows x 128 cols ----
    {
        int r = mrow0 + (lane >> 2);
        size_t gt = (size_t)tile * 128 + r;
        float* row0 = out + gt * EMBED + nq * 128;
        float* row1 = row0 + 8 * EMBED;
        #pragma unroll
        for (int nb = 0; nb < 16; nb++) {
            int c = nb * 8 + (lane & 3) * 2;
            *reinterpret_cast<float2*>(row0 + c) = make_float2(acc[nb][0], acc[nb][1]);
            *reinterpret_cast<float2*>(row1 + c) = make_float2(acc[nb][2], acc[nb][3]);
        }
    }
}

// ---------------- launch ----------------
extern "C" void kernel_launch(void* const* d_in, const int* in_sizes, int n_in,
                              void* d_out, int out_size) {
    const float* x     = (const float*)d_in[0];
    const float* theta = (const float*)d_in[1];
    const float* W1    = (const float*)d_in[2];
    const float* W2    = (const float*)d_in[3];
    float* out = (float*)d_out;

    cudaFuncSetAttribute(ffq_mma, cudaFuncAttributeMaxDynamicSharedMemorySize, SMEM_TOTAL);

    // W2/W1 fp32 -> fp16 scratch (deterministic each call)
    wcvt_kernel<<<(EMBED * FFN) / (256 * 4), 256>>>(W2, W1);

    // fused GEMM: 1024 CTAs = 256 token tiles x 4 N-quarters, 2 CTAs/SM
    ffq_mma<<<NCTAS, THREADS, SMEM_TOTAL>>>(x, theta, out);
}